// round 7
// baseline (speedup 1.0000x reference)
#include <cuda_runtime.h>
#include <cuda_bf16.h>
#include <math.h>

#define BB 4
#define LL 64
#define DD 64
#define RELN 16
#define NEGV (-1e9f)
#define LOSS_SCALE 4398046511104.0   // 2^42
#define PADR 69                      // padded row stride (floats), conflict-free

// ---------------- fast math helpers ------------------------------------------
__device__ __forceinline__ float rcpa(float x) {
    float y; asm("rcp.approx.f32 %0, %1;" : "=f"(y) : "f"(x)); return y;
}
__device__ __forceinline__ float sigm(float x)  { return rcpa(1.f + __expf(-x)); }
__device__ __forceinline__ float tanha(float x) { return 1.f - 2.f * rcpa(__expf(2.f * x) + 1.f); }

// ---------------- packed f32x2 FMA helpers ------------------------------------
__device__ __forceinline__ void fma2(unsigned long long& d,
                                     unsigned long long a, unsigned long long b) {
    asm("fma.rn.f32x2 %0, %1, %2, %0;" : "+l"(d) : "l"(a), "l"(b));
}
__device__ __forceinline__ void unpack2(unsigned long long v, float& x, float& y) {
    asm("mov.b64 {%0,%1}, %2;" : "=f"(x), "=f"(y) : "l"(v));
}
__device__ __forceinline__ float dot64(const ulonglong2* __restrict__ a,
                                       const ulonglong2* __restrict__ b) {
    unsigned long long a0 = 0ULL, a1 = 0ULL, a2 = 0ULL, a3 = 0ULL;
#pragma unroll
    for (int q = 0; q < 16; q += 2) {
        ulonglong2 x = a[q], y = b[q];
        ulonglong2 x2 = a[q + 1], y2 = b[q + 1];
        fma2(a0, x.x, y.x);  fma2(a1, x.y, y.y);
        fma2(a2, x2.x, y2.x); fma2(a3, x2.y, y2.y);
    }
    float s0, s1, s2, s3, s4, s5, s6, s7;
    unpack2(a0, s0, s1); unpack2(a1, s2, s3);
    unpack2(a2, s4, s5); unpack2(a3, s6, s7);
    return ((s0 + s1) + (s2 + s3)) + ((s4 + s5) + (s6 + s7));
}

// ---------------- global scratch & sync ---------------------------------------
__device__ __align__(16) float g_o[BB * LL * DD];
__device__ __align__(16) float g_s[BB * RELN * LL * LL];
__device__ __align__(16) float g_gx[BB * LL * 3 * DD];
__device__ unsigned long long g_lossint;
__device__ unsigned int g_pBb[BB];
__device__ unsigned int g_loss;

// ================== K1: relation score maps S_k = O M_k O^T ===================
// grid 256: b=blk>>6, k=(blk>>2)&15, q4=blk&3 (16-col j slab); 128 threads
__global__ void __launch_bounds__(128)
k1_scores(const int* __restrict__ x, const float* __restrict__ emb,
          const float* __restrict__ rel) {
    __shared__ int sx[LL];
    __shared__ float so[LL * PADR];
    __shared__ float srel[LL * PADR];
    __shared__ float sv[16 * DD];

    int blk = blockIdx.x, tid = threadIdx.x;
    int b = blk >> 6, k = (blk >> 2) & 15, q4 = blk & 3;

    if (tid < LL) sx[tid] = x[b * LL + tid];
    __syncthreads();
    for (int idx = tid; idx < LL * DD; idx += 128) {
        int l = idx >> 6, d = idx & 63;
        so[l * PADR + d] = emb[sx[l] * DD + d];        // coalesced per row
    }
    if (k > 0) {
        for (int idx = tid; idx < DD * DD; idx += 128) {
            srel[(idx >> 6) * PADR + (idx & 63)] = rel[k * DD * DD + idx];  // coalesced
        }
    }
    __syncthreads();

    if (k == 0) {
        if (q4 == 0) {
            for (int idx = tid; idx < LL * DD; idx += 128)
                g_o[b * LL * DD + idx] = so[(idx >> 6) * PADR + (idx & 63)];
        }
        return;
    }

    int d = tid & 63, jgrp = tid >> 6;     // jgrp 0..1
    // row d of M_k in registers (conflict-free shared reads)
    float m[64];
#pragma unroll
    for (int e = 0; e < 64; e++) m[e] = srel[d * PADR + e];
    // v[jl][d] = M_k[d,:] . o[j,:]
    for (int jj = 0; jj < 8; jj++) {
        int jl = jgrp * 8 + jj;
        int j  = q4 * 16 + jl;
        float acc = 0.f;
        const float* sr = so + j * PADR;   // broadcast reads
#pragma unroll
        for (int e = 0; e < 64; e++) acc += m[e] * sr[e];
        sv[jl * DD + d] = acc;
    }
    __syncthreads();
    // S[i][j] = o[i,:] . v[jl,:]
    int i = tid & 63;
    float oi[64];
#pragma unroll
    for (int e = 0; e < 64; e++) oi[e] = so[i * PADR + e];
    float res[8];
    for (int jj = 0; jj < 8; jj++) {
        int jl = jgrp * 8 + jj;
        float acc = 0.f;
        const float* vv = sv + jl * DD;    // broadcast
#pragma unroll
        for (int e = 0; e < 64; e++) acc += oi[e] * vv[e];
        res[jj] = acc;
    }
    float4* dst = reinterpret_cast<float4*>(
        g_s + (((b * RELN + k) * LL + i) * LL) + q4 * 16 + jgrp * 8);
    dst[0] = make_float4(res[0], res[1], res[2], res[3]);
    dst[1] = make_float4(res[4], res[5], res[6], res[7]);
}

// ================== K2: attention + GRU + tail (fused) ========================
// grid 32: b=blk>>3, oct=blk&7 (8 i's per block); 256 threads; ~93KB dyn smem
struct PC {
    float shseq[LL][DD];     // 4096
    float sh[DD];            // 64
    float sgh[3 * DD];       // 192
    float sga[LL][3];        // 192
    float sa[LL];            // 64
    float sw[LL];            // 64
    float sc[DD];            // 64
    float sh1[DD / 2];       // 32
    float slog[2];
    float wred[4];
    int smaxl;
};

#define DSM_FLOATS (4416 + 4416 + 13248 + 64 + 192 + 1024)
#define DSM_BYTES  (DSM_FLOATS * 4)

__global__ void __launch_bounds__(256)
k2_fused(const int* __restrict__ r, const int* __restrict__ lv,
         const int* __restrict__ yv,
         const float* __restrict__ attW, const float* __restrict__ attb,
         const float* __restrict__ gWih, const float* __restrict__ gbih,
         const float* __restrict__ Whh,  const float* __restrict__ bhh,
         const float* __restrict__ oWih, const float* __restrict__ oWhh,
         const float* __restrict__ obih, const float* __restrict__ obhh,
         const float* __restrict__ W1, const float* __restrict__ b1,
         const float* __restrict__ W2, const float* __restrict__ b2,
         float* __restrict__ out, int out_size) {
    extern __shared__ __align__(16) float dsm[];
    float* sob   = dsm;                 // [64][PADR]
    float* sawT  = sob   + LL * PADR;   // attW transposed [q][PADR]
    float* sgW   = sawT  + DD * PADR;   // gWih rows [192][PADR]
    float* sattb = sgW   + 192 * PADR;  // 64
    float* sgbih = sattb + 64;          // 192
    float* gsc   = sgbih + 192;         // 4 groups x 256

    int blk = blockIdx.x, tid = threadIdx.x;
    int b = blk >> 3, oct = blk & 7;
    int grp = tid >> 6, lane = tid & 63;

    // ---- stage (all coalesced global reads) ----
    for (int idx = tid; idx < LL * DD; idx += 256)
        sob[(idx >> 6) * PADR + (idx & 63)] = g_o[b * LL * DD + idx];
    for (int idx = tid; idx < DD * DD; idx += 256) {
        int dd = idx >> 6, q = idx & 63;
        sawT[q * PADR + dd] = attW[idx];          // transpose into shared
    }
    for (int idx = tid; idx < 192 * DD; idx += 256)
        sgW[(idx >> 6) * PADR + (idx & 63)] = gWih[idx];
    if (tid < DD) sattb[tid] = attb[tid];
    if (tid < 192) sgbih[tid] = gbih[tid];
    __syncthreads();

    float* sp   = gsc + grp * 256;
    float* sctx = sp + 64;
    float* sso2 = sctx + 64;
    float* red  = sso2 + 64;    // 8 floats
    int wig = (tid >> 5) & 1;   // warp-in-group

    for (int ii = 0; ii < 2; ii++) {
        int i = oct * 8 + grp * 2 + ii;
        int j = lane;
        int rj = r[(b * LL + i) * LL + j];
        float s = (rj > 0) ? g_s[(((b * RELN + rj) * LL + i) * LL) + j] : NEGV;
        float mx = s;
#pragma unroll
        for (int off = 16; off; off >>= 1)
            mx = fmaxf(mx, __shfl_xor_sync(0xFFFFFFFFu, mx, off));
        if ((lane & 31) == 0) red[wig] = mx;
        __syncthreads();
        mx = fmaxf(red[0], red[1]);
        float e = __expf(s - mx);
        float ss = e;
#pragma unroll
        for (int off = 16; off; off >>= 1) ss += __shfl_xor_sync(0xFFFFFFFFu, ss, off);
        if ((lane & 31) == 0) red[2 + wig] = ss;
        sp[j] = e;
        __syncthreads();
        float inv = rcpa(red[2] + red[3]);
        // context (conflict-free column reads + broadcast weights)
        {
            float acc = 0.f;
#pragma unroll 8
            for (int jj = 0; jj < LL; jj++) acc += sp[jj] * sob[jj * PADR + lane];
            sctx[lane] = acc * inv;
        }
        __syncthreads();
        // so2 = attW . ctx (transposed layout: conflict-free)
        {
            float acc = sattb[lane];
#pragma unroll 8
            for (int q = 0; q < DD; q++) acc += sawT[q * PADR + lane] * sctx[q];
            sso2[lane] = acc;
        }
        __syncthreads();
        // gx rows lane, lane+64, lane+128
        float* gxo = g_gx + (b * LL + i) * (3 * DD);
#pragma unroll
        for (int t3 = 0; t3 < 3; t3++) {
            int g = t3 * DD + lane;
            float acc = sgbih[g];
            const float* wrow = sgW + g * PADR;
#pragma unroll 8
            for (int q = 0; q < DD; q++) acc += wrow[q] * sso2[q];
            gxo[g] = acc;
        }
        __syncthreads();
    }

    __threadfence();
    if (tid == 0) atomicAdd(&g_pBb[b], 1u);

    if (oct != 0) return;

    // wait for this batch's 8 blocks
    if (tid == 0) {
        while (*(volatile unsigned int*)&g_pBb[b] < 8u) __nanosleep(64);
    }
    __syncthreads();
    __threadfence();

    // ================= phase C: GRU + out-GRU + classifier ===================
    PC* C = reinterpret_cast<PC*>(dsm);
    int k = tid;

    ulonglong2 w[16];
    float bk = 0.f;
    if (k < 192) {
        const ulonglong2* wr = reinterpret_cast<const ulonglong2*>(Whh + k * DD);
#pragma unroll
        for (int qq = 0; qq < 16; qq++) w[qq] = wr[qq];
        bk = bhh[k];
    }
    if (k < DD) C->sh[k] = 0.f;
    if (k == 0) {
        int m = lv[0];
#pragma unroll
        for (int i = 1; i < BB; i++) m = max(m, lv[i]);
        C->smaxl = m + 1;
    }
    __syncthreads();

    const float* gxb = g_gx + b * LL * (3 * DD);
    float xr = 0.f, xz = 0.f, xn = 0.f;
    if (k < DD) { xr = gxb[k]; xz = gxb[DD + k]; xn = gxb[2 * DD + k]; }

    for (int l = 0; l < LL; l++) {
        if (k < 192) {
            const ulonglong2* h2 = reinterpret_cast<const ulonglong2*>(C->sh);
            unsigned long long a0 = 0ULL, a1 = 0ULL, a2 = 0ULL, a3 = 0ULL;
#pragma unroll
            for (int qq = 0; qq < 16; qq += 2) {
                ulonglong2 hA = h2[qq], hB = h2[qq + 1];
                fma2(a0, w[qq].x, hA.x);     fma2(a1, w[qq].y, hA.y);
                fma2(a2, w[qq + 1].x, hB.x); fma2(a3, w[qq + 1].y, hB.y);
            }
            float s0, s1, s2, s3, s4, s5, s6, s7;
            unpack2(a0, s0, s1); unpack2(a1, s2, s3);
            unpack2(a2, s4, s5); unpack2(a3, s6, s7);
            C->sgh[k] = bk + ((s0 + s1) + (s2 + s3)) + ((s4 + s5) + (s6 + s7));
        }
        __syncthreads();
        if (k < DD) {
            float rg = sigm(xr + C->sgh[k]);
            float zg = sigm(xz + C->sgh[DD + k]);
            float ng = tanha(xn + rg * C->sgh[2 * DD + k]);
            float hnew = (1.f - zg) * ng + zg * C->sh[k];
            C->sh[k] = hnew;
            C->shseq[l][k] = hnew;
            if (l + 1 < LL) {
                const float* nx = gxb + (l + 1) * 3 * DD;
                xr = nx[k]; xz = nx[DD + k]; xn = nx[2 * DD + k];
            }
        }
        __syncthreads();
    }

    // out-GRU input projections: 192 dots, one per thread
    if (k < 192) {
        int l = k & 63, g = k >> 6;
        C->sga[l][g] = obih[g] +
            dot64(reinterpret_cast<const ulonglong2*>(C->shseq[l]),
                  reinterpret_cast<const ulonglong2*>(oWih + g * DD));
    }
    __syncthreads();

    if (k == 0) {
        float h = 0.f;
        float w0 = oWhh[0], w1 = oWhh[1], wn = oWhh[2];
        float c0 = obhh[0], c1 = obhh[1], cn = obhh[2];
        for (int l = 0; l < LL; l++) {
            float rg = sigm(C->sga[l][0] + h * w0 + c0);
            float zg = sigm(C->sga[l][1] + h * w1 + c1);
            float ng = tanha(C->sga[l][2] + rg * (h * wn + cn));
            h = (1.f - zg) * ng + zg * h;
            C->sa[l] = h;
        }
    }
    __syncthreads();

    if (k < DD) {
        float v = (k < C->smaxl) ? C->sa[k] : NEGV;
        float mx = v;
#pragma unroll
        for (int off = 16; off; off >>= 1)
            mx = fmaxf(mx, __shfl_xor_sync(0xFFFFFFFFu, mx, off));
        if ((k & 31) == 0) C->wred[k >> 5] = mx;
        C->sa[k] = v;
    }
    __syncthreads();
    if (k < DD) {
        float mx = fmaxf(C->wred[0], C->wred[1]);
        float e = __expf(C->sa[k] - mx);
        float ss = e;
#pragma unroll
        for (int off = 16; off; off >>= 1) ss += __shfl_xor_sync(0xFFFFFFFFu, ss, off);
        if ((k & 31) == 0) C->wred[2 + (k >> 5)] = ss;
        C->sw[k] = e;
    }
    __syncthreads();
    if (k < DD) {
        float inv = rcpa(C->wred[2] + C->wred[3]);
        float acc = 0.f;
#pragma unroll 8
        for (int l = 0; l < LL; l++) acc += C->sw[l] * C->shseq[l][k];
        C->sc[k] = acc * inv;
    }
    __syncthreads();
    if (k < 32) {
        float acc = b1[k] +
            dot64(reinterpret_cast<const ulonglong2*>(W1 + k * DD),
                  reinterpret_cast<const ulonglong2*>(C->sc));
        C->sh1[k] = fmaxf(acc, 0.f);
    }
    __syncthreads();
    if (k < 2) {
        const float* wr2 = W2 + k * 32;
        float acc = b2[k];
#pragma unroll
        for (int m = 0; m < 32; m++) acc += C->sh1[m] * wr2[m];
        C->slog[k] = acc;
    }
    __syncthreads();

    if (k == 0) {
        float a0 = C->slog[0], a1 = C->slog[1];
        float mx = fmaxf(a0, a1);
        float e0 = __expf(a0 - mx), e1 = __expf(a1 - mx);
        float z = e0 + e1;
        float invz = rcpa(z);
        if (2 * b < out_size)     out[2 * b]     = e0 * invz;
        if (2 * b + 1 < out_size) out[2 * b + 1] = e1 * invz;
        float chosen = (yv[b] == 0) ? a0 : a1;
        float t = -(chosen - mx - __logf(z));
        atomicAdd(&g_lossint, (unsigned long long)((double)t * LOSS_SCALE));
        __threadfence();
        unsigned int c = atomicAdd(&g_loss, 1u);
        if (c == 3u) {
            unsigned long long s = atomicAdd(&g_lossint, 0ULL);
            if (out_size > 8)
                out[8] = (float)((double)s * (1.0 / (4.0 * LOSS_SCALE)));
            for (int i = 9; i < out_size; i++) out[i] = 0.f;
            g_loss = 0u; g_lossint = 0ULL;
#pragma unroll
            for (int i = 0; i < BB; i++) g_pBb[i] = 0u;
            __threadfence();
        }
    }
}

// ---------------- launch ------------------------------------------------------
extern "C" void kernel_launch(void* const* d_in, const int* in_sizes, int n_in,
                              void* d_out, int out_size) {
    const int*   x    = (const int*)  d_in[0];
    const int*   y    = (const int*)  d_in[1];
    const int*   r    = (const int*)  d_in[2];
    const int*   l    = (const int*)  d_in[3];
    const float* emb  = (const float*)d_in[4];
    const float* rel  = (const float*)d_in[5];
    const float* attW = (const float*)d_in[6];
    const float* attb = (const float*)d_in[7];
    const float* gWih = (const float*)d_in[8];
    const float* gWhh = (const float*)d_in[9];
    const float* gbih = (const float*)d_in[10];
    const float* gbhh = (const float*)d_in[11];
    const float* oWih = (const float*)d_in[12];
    const float* oWhh = (const float*)d_in[13];
    const float* obih = (const float*)d_in[14];
    const float* obhh = (const float*)d_in[15];
    const float* W1   = (const float*)d_in[16];
    const float* b1   = (const float*)d_in[17];
    const float* W2   = (const float*)d_in[18];
    const float* b2   = (const float*)d_in[19];

    static int smem_set = 0;
    if (!smem_set) {
        cudaFuncSetAttribute(k2_fused, cudaFuncAttributeMaxDynamicSharedMemorySize,
                             DSM_BYTES);
        smem_set = 1;
    }

    k1_scores<<<BB * RELN * 4, 128>>>(x, emb, rel);
    k2_fused<<<BB * 8, 256, DSM_BYTES>>>(r, l, y, attW, attb, gWih, gbih,
                                         gWhh, gbhh, oWih, oWhh, obih, obhh,
                                         W1, b1, W2, b2,
                                         (float*)d_out, out_size);
}

// round 8
// speedup vs baseline: 1.3737x; 1.3737x over previous
#include <cuda_runtime.h>
#include <cuda_bf16.h>
#include <math.h>

#define BB 4
#define LL 64
#define DD 64
#define RELN 16
#define NEGV (-1e9f)
#define LOSS_SCALE 4398046511104.0   // 2^42

// ---------------- fast math helpers ------------------------------------------
__device__ __forceinline__ float rcpa(float x) {
    float y; asm("rcp.approx.f32 %0, %1;" : "=f"(y) : "f"(x)); return y;
}
__device__ __forceinline__ float sigm(float x)  { return rcpa(1.f + __expf(-x)); }
__device__ __forceinline__ float tanha(float x) { return 1.f - 2.f * rcpa(__expf(2.f * x) + 1.f); }

// ---------------- packed f32x2 FMA helpers ------------------------------------
__device__ __forceinline__ void fma2(unsigned long long& d,
                                     unsigned long long a, unsigned long long b) {
    asm("fma.rn.f32x2 %0, %1, %2, %0;" : "+l"(d) : "l"(a), "l"(b));
}
__device__ __forceinline__ void unpack2(unsigned long long v, float& x, float& y) {
    asm("mov.b64 {%0,%1}, %2;" : "=f"(x), "=f"(y) : "l"(v));
}
__device__ __forceinline__ float dot64(const ulonglong2* __restrict__ a,
                                       const ulonglong2* __restrict__ b) {
    unsigned long long a0 = 0ULL, a1 = 0ULL, a2 = 0ULL, a3 = 0ULL;
#pragma unroll
    for (int q = 0; q < 16; q += 2) {
        ulonglong2 x = a[q], y = b[q];
        ulonglong2 x2 = a[q + 1], y2 = b[q + 1];
        fma2(a0, x.x, y.x);  fma2(a1, x.y, y.y);
        fma2(a2, x2.x, y2.x); fma2(a3, x2.y, y2.y);
    }
    float s0, s1, s2, s3, s4, s5, s6, s7;
    unpack2(a0, s0, s1); unpack2(a1, s2, s3);
    unpack2(a2, s4, s5); unpack2(a3, s6, s7);
    return ((s0 + s1) + (s2 + s3)) + ((s4 + s5) + (s6 + s7));
}

// ---------------- scratch ------------------------------------------------------
__device__ __align__(16) float g_o[BB * LL * DD];
__device__ __align__(16) float g_v[BB * RELN * LL * DD];
__device__ __align__(16) float g_gx[BB * LL * 3 * DD];
__device__ unsigned long long g_lossint;
__device__ unsigned int g_loss;

// ---------------- KA: embedding gather + relation matvec (R3-proven) ----------
__global__ void ka_embed_relmat(const int* __restrict__ x,
                                const float* __restrict__ emb,
                                const float* __restrict__ rel) {
    int b    = blockIdx.x >> 5;
    int k    = (blockIdx.x >> 1) & 15;
    int half = blockIdx.x & 1;
    __shared__ __align__(16) float so[LL * DD];
    int tid = threadIdx.x;

    for (int i = tid; i < LL * DD; i += 256) {
        int l = i >> 6;
        int d = i & 63;
        so[i] = emb[x[b * LL + l] * DD + d];
    }
    __syncthreads();

    if (k == 0 && half == 0) {
        for (int i = tid; i < LL * DD; i += 256) g_o[b * LL * DD + i] = so[i];
    }

    int d  = tid & 63;
    int jg = tid >> 6;
    ulonglong2 m[16];
    const ulonglong2* mrow = reinterpret_cast<const ulonglong2*>(rel + k * DD * DD + d * DD);
#pragma unroll
    for (int q = 0; q < 16; q++) m[q] = mrow[q];

    int jbase = half * 32 + jg * 8;
#pragma unroll
    for (int jj = 0; jj < 8; jj++) {
        int j = jbase + jj;
        g_v[(((b * RELN + k) * LL + j) * DD) + d] =
            dot64(m, reinterpret_cast<const ulonglong2*>(so + j * DD));
    }
}

// ---------------- KB: attention column (R3-proven) ----------------------------
__global__ void kb_attn(const int* __restrict__ r,
                        const float* __restrict__ attW,
                        const float* __restrict__ attb,
                        const float* __restrict__ gWih,
                        const float* __restrict__ gbih) {
    int b = blockIdx.x >> 6;
    int i = blockIdx.x & 63;
    int tid = threadIdx.x;   // 64

    __shared__ float sob[LL][DD + 1];
    __shared__ __align__(16) float soi[DD];
    __shared__ float sp[LL];
    __shared__ __align__(16) float sctx[DD];
    __shared__ __align__(16) float so2[DD];
    __shared__ float wmax[2], wsum[2];

    const float* ob = g_o + b * LL * DD;
    for (int jj = 0; jj < LL; jj++) sob[jj][tid] = ob[jj * DD + tid];
    __syncthreads();
    soi[tid] = sob[i][tid];
    __syncthreads();

    int j = tid;
    int rj = r[(b * LL + i) * LL + j];
    float s;
    if (rj > 0) {
        s = dot64(reinterpret_cast<const ulonglong2*>(
                      g_v + (((b * RELN + rj) * LL + j) * DD)),
                  reinterpret_cast<const ulonglong2*>(soi));
    } else {
        s = NEGV;
    }

    float mx = s;
#pragma unroll
    for (int off = 16; off; off >>= 1) mx = fmaxf(mx, __shfl_xor_sync(0xFFFFFFFFu, mx, off));
    if ((tid & 31) == 0) wmax[tid >> 5] = mx;
    __syncthreads();
    mx = fmaxf(wmax[0], wmax[1]);
    float e = __expf(s - mx);
    float ss = e;
#pragma unroll
    for (int off = 16; off; off >>= 1) ss += __shfl_xor_sync(0xFFFFFFFFu, ss, off);
    if ((tid & 31) == 0) wsum[tid >> 5] = ss;
    __syncthreads();
    float inv = rcpa(wsum[0] + wsum[1]);
    sp[tid] = e * inv;
    __syncthreads();

    {
        float acc = 0.f;
        for (int jj = 0; jj < LL; jj++) acc += sp[jj] * sob[jj][tid];
        sctx[tid] = acc;
    }
    __syncthreads();

    so2[tid] = attb[tid] +
               dot64(reinterpret_cast<const ulonglong2*>(attW + tid * DD),
                     reinterpret_cast<const ulonglong2*>(sctx));
    __syncthreads();

    float* gxout = g_gx + (b * LL + i) * (3 * DD);
#pragma unroll
    for (int gset = 0; gset < 3; gset++) {
        int g = gset * DD + tid;
        gxout[g] = gbih[g] +
                   dot64(reinterpret_cast<const ulonglong2*>(gWih + g * DD),
                         reinterpret_cast<const ulonglong2*>(so2));
    }
}

// ---------------- KC: single-barrier GRU + tail + loss (64 threads) -----------
__global__ void __launch_bounds__(64)
kc_fused(const float* __restrict__ Whh, const float* __restrict__ bhh,
         const int* __restrict__ lv, const int* __restrict__ yv,
         const float* __restrict__ oWih, const float* __restrict__ oWhh,
         const float* __restrict__ obih, const float* __restrict__ obhh,
         const float* __restrict__ W1, const float* __restrict__ b1,
         const float* __restrict__ W2, const float* __restrict__ b2,
         float* __restrict__ out, int out_size) {
    int b = blockIdx.x;
    int k = threadIdx.x;   // 0..63

    __shared__ __align__(16) float sh[DD];
    __shared__ __align__(16) float shseq[LL][DD];
    __shared__ float sga[LL][3];
    __shared__ float sa[LL];
    __shared__ float sw[LL];
    __shared__ __align__(16) float sc[DD];
    __shared__ __align__(16) float sh1[DD / 2];
    __shared__ float slog[2];
    __shared__ float wred[4];
    __shared__ int smaxl;

    // thread k owns all three gate rows (r=k, z=64+k, n=128+k): 192 regs of weights
    ulonglong2 wR[16], wZ[16], wN[16];
    {
        const ulonglong2* p0 = reinterpret_cast<const ulonglong2*>(Whh + k * DD);
        const ulonglong2* p1 = reinterpret_cast<const ulonglong2*>(Whh + (DD + k) * DD);
        const ulonglong2* p2 = reinterpret_cast<const ulonglong2*>(Whh + (2 * DD + k) * DD);
#pragma unroll
        for (int q = 0; q < 16; q++) { wR[q] = p0[q]; wZ[q] = p1[q]; wN[q] = p2[q]; }
    }
    float bR = bhh[k], bZ = bhh[DD + k], bN = bhh[2 * DD + k];

    if (k == 0) {
        int m = lv[0];
#pragma unroll
        for (int i = 1; i < BB; i++) m = max(m, lv[i]);
        smaxl = m + 1;
    }

    const float* gxb = g_gx + b * LL * (3 * DD);
    float xr = gxb[k], xz = gxb[DD + k], xn = gxb[2 * DD + k];
    float hown = 0.f;

    // ---- step 0: h = 0 -> gh = bhh ----
    {
        float rg = sigm(xr + bR);
        float zg = sigm(xz + bZ);
        float ng = tanha(xn + rg * bN);
        hown = (1.f - zg) * ng;
        sh[k] = hown;
        shseq[0][k] = hown;
        const float* nx = gxb + 3 * DD;
        xr = nx[k]; xz = nx[DD + k]; xn = nx[2 * DD + k];
    }
    __syncthreads();

    // ---- steps 1..63: ONE barrier per step, gates fused in-thread ----
    for (int l = 1; l < LL; l++) {
        const ulonglong2* h2 = reinterpret_cast<const ulonglong2*>(sh);
        unsigned long long aR0 = 0ULL, aR1 = 0ULL, aZ0 = 0ULL, aZ1 = 0ULL,
                           aN0 = 0ULL, aN1 = 0ULL;
#pragma unroll
        for (int q = 0; q < 16; q++) {
            ulonglong2 hq = h2[q];            // one shared quad feeds 3 gates
            fma2(aR0, wR[q].x, hq.x); fma2(aR1, wR[q].y, hq.y);
            fma2(aZ0, wZ[q].x, hq.x); fma2(aZ1, wZ[q].y, hq.y);
            fma2(aN0, wN[q].x, hq.x); fma2(aN1, wN[q].y, hq.y);
        }
        float r0, r1, r2, r3, z0, z1, z2, z3, n0, n1, n2, n3;
        unpack2(aR0, r0, r1); unpack2(aR1, r2, r3);
        unpack2(aZ0, z0, z1); unpack2(aZ1, z2, z3);
        unpack2(aN0, n0, n1); unpack2(aN1, n2, n3);
        float hr = bR + (r0 + r1) + (r2 + r3);
        float hz = bZ + (z0 + z1) + (z2 + z3);
        float hn = bN + (n0 + n1) + (n2 + n3);
        float rg = sigm(xr + hr);
        float zg = sigm(xz + hz);
        float ng = tanha(xn + rg * hn);
        hown = (1.f - zg) * ng + zg * hown;
        __syncthreads();                      // everyone done READING old sh
        sh[k] = hown;
        shseq[l][k] = hown;
        if (l + 1 < LL) {
            const float* nx = gxb + (l + 1) * 3 * DD;
            xr = nx[k]; xz = nx[DD + k]; xn = nx[2 * DD + k];
        }
        __syncthreads();                      // new sh visible
    }

    // ---- out-GRU input projections: 3 dots per thread ----
#pragma unroll
    for (int g = 0; g < 3; g++) {
        sga[k][g] = obih[g] +
            dot64(reinterpret_cast<const ulonglong2*>(shseq[k]),
                  reinterpret_cast<const ulonglong2*>(oWih + g * DD));
    }
    __syncthreads();

    if (k == 0) {
        float h = 0.f;
        float w0 = oWhh[0], w1 = oWhh[1], wn = oWhh[2];
        float c0 = obhh[0], c1 = obhh[1], cn = obhh[2];
        for (int l = 0; l < LL; l++) {
            float rg = sigm(sga[l][0] + h * w0 + c0);
            float zg = sigm(sga[l][1] + h * w1 + c1);
            float ng = tanha(sga[l][2] + rg * (h * wn + cn));
            h = (1.f - zg) * ng + zg * h;
            sa[l] = h;
        }
    }
    __syncthreads();

    // masked softmax over L
    {
        float v = (k < smaxl) ? sa[k] : NEGV;
        float mx = v;
#pragma unroll
        for (int off = 16; off; off >>= 1)
            mx = fmaxf(mx, __shfl_xor_sync(0xFFFFFFFFu, mx, off));
        if ((k & 31) == 0) wred[k >> 5] = mx;
        sa[k] = v;
    }
    __syncthreads();
    {
        float mx = fmaxf(wred[0], wred[1]);
        float e = __expf(sa[k] - mx);
        float ss = e;
#pragma unroll
        for (int off = 16; off; off >>= 1) ss += __shfl_xor_sync(0xFFFFFFFFu, ss, off);
        if ((k & 31) == 0) wred[2 + (k >> 5)] = ss;
        sw[k] = e;
    }
    __syncthreads();
    {
        float inv = rcpa(wred[2] + wred[3]);
        float acc = 0.f;
#pragma unroll 8
        for (int l = 0; l < LL; l++) acc += sw[l] * shseq[l][k];
        sc[k] = acc * inv;
    }
    __syncthreads();
    if (k < 32) {
        float acc = b1[k] +
            dot64(reinterpret_cast<const ulonglong2*>(W1 + k * DD),
                  reinterpret_cast<const ulonglong2*>(sc));
        sh1[k] = fmaxf(acc, 0.f);
    }
    __syncthreads();
    if (k < 2) {
        const float* wr2 = W2 + k * 32;
        float acc = b2[k];
#pragma unroll
        for (int m = 0; m < 32; m++) acc += sh1[m] * wr2[m];
        slog[k] = acc;
    }
    __syncthreads();

    if (k == 0) {
        float a0 = slog[0], a1 = slog[1];
        float mx = fmaxf(a0, a1);
        float e0 = __expf(a0 - mx), e1 = __expf(a1 - mx);
        float z = e0 + e1;
        float invz = rcpa(z);
        if (2 * b < out_size)     out[2 * b]     = e0 * invz;
        if (2 * b + 1 < out_size) out[2 * b + 1] = e1 * invz;
        float chosen = (yv[b] == 0) ? a0 : a1;
        float t = -(chosen - mx - __logf(z));
        atomicAdd(&g_lossint, (unsigned long long)((double)t * LOSS_SCALE));
        __threadfence();
        unsigned int c = atomicAdd(&g_loss, 1u);
        if (c == 3u) {
            unsigned long long s = atomicAdd(&g_lossint, 0ULL);
            if (out_size > 8)
                out[8] = (float)((double)s * (1.0 / (4.0 * LOSS_SCALE)));
            for (int i = 9; i < out_size; i++) out[i] = 0.f;
            g_loss = 0u; g_lossint = 0ULL;
            __threadfence();
        }
    }
}

// ---------------- launch ------------------------------------------------------
extern "C" void kernel_launch(void* const* d_in, const int* in_sizes, int n_in,
                              void* d_out, int out_size) {
    const int*   x    = (const int*)  d_in[0];
    const int*   y    = (const int*)  d_in[1];
    const int*   r    = (const int*)  d_in[2];
    const int*   l    = (const int*)  d_in[3];
    const float* emb  = (const float*)d_in[4];
    const float* rel  = (const float*)d_in[5];
    const float* attW = (const float*)d_in[6];
    const float* attb = (const float*)d_in[7];
    const float* gWih = (const float*)d_in[8];
    const float* gWhh = (const float*)d_in[9];
    const float* gbih = (const float*)d_in[10];
    const float* gbhh = (const float*)d_in[11];
    const float* oWih = (const float*)d_in[12];
    const float* oWhh = (const float*)d_in[13];
    const float* obih = (const float*)d_in[14];
    const float* obhh = (const float*)d_in[15];
    const float* W1   = (const float*)d_in[16];
    const float* b1   = (const float*)d_in[17];
    const float* W2   = (const float*)d_in[18];
    const float* b2   = (const float*)d_in[19];

    ka_embed_relmat<<<BB * RELN * 2, 256>>>(x, emb, rel);
    kb_attn<<<BB * LL, 64>>>(r, attW, attb, gWih, gbih);
    kc_fused<<<BB, 64>>>(gWhh, gbhh, l, y, oWih, oWhh, obih, obhh,
                         W1, b1, W2, b2, (float*)d_out, out_size);
}